// round 17
// baseline (speedup 1.0000x reference)
#include <cuda_runtime.h>
#include <cuda_fp16.h>
#include <math.h>
#include <stdint.h>

#define NPTS 1024
#define KNB 20
#define BATCH 8
#define CEPS 1e-5f
#define CSLOPE 0.2f

// ---------------- scratch (no allocations allowed) ----------------
// all split-fp16 operands stored element-major: row = elem, cols = k-pair words
__device__ uint32_t g_catH[(size_t)BATCH * NPTS * 256];   // [b*NPTS+n][cp]
__device__ uint32_t g_catL[(size_t)BATCH * NPTS * 256];
__device__ float    g_gram[(size_t)BATCH * NPTS * NPTS];
__device__ float    g_xx[BATCH * NPTS];
__device__ int      g_idx[(size_t)BATCH * NPTS * KNB];
__device__ float    g_Z[(size_t)BATCH * NPTS * 512];
__device__ float    g_h1[BATCH * 512];
__device__ uint32_t g_WtH[45568], g_WtL[45568];           // [j][kp] per segment
__device__ uint32_t g_weTH[1024 * 256], g_weTL[1024 * 256]; // [o][p]
__device__ uint32_t g_xH[BATCH * NPTS * 4], g_xL[BATCH * NPTS * 4]; // [b*NPTS+n][4]
__device__ float    g_pmax[BATCH * NPTS * 8];
__device__ float    g_psum[BATCH * NPTS * 8];

// Wt segment word offsets: sizes 128x4, 128x32, 256x32, 512x64
#define WSEG0 0
#define WSEG1 512
#define WSEG2 4608
#define WSEG3 12800
#define WTOTU 45568

// ================= helpers =================
__device__ __forceinline__ uint32_t packh(float a, float b) {
    __half2 h = __halves2half2(__float2half_rn(a), __float2half_rn(b));
    return *(uint32_t*)&h;
}
__device__ __forceinline__ uint32_t packl(float a, float b) {
    float ra = a - __half2float(__float2half_rn(a));
    float rb = b - __half2float(__float2half_rn(b));
    __half2 h = __halves2half2(__float2half_rn(ra), __float2half_rn(rb));
    return *(uint32_t*)&h;
}
__device__ __forceinline__ void mma16(float* c, const uint32_t* a, const uint32_t* b) {
    asm volatile(
        "mma.sync.aligned.m16n8k16.row.col.f32.f16.f16.f32 "
        "{%0,%1,%2,%3}, {%4,%5,%6,%7}, {%8,%9}, {%0,%1,%2,%3};\n"
        : "+f"(c[0]), "+f"(c[1]), "+f"(c[2]), "+f"(c[3])
        : "r"(a[0]), "r"(a[1]), "r"(a[2]), "r"(a[3]), "r"(b[0]), "r"(b[1]));
}
__device__ __forceinline__ void ldsm4(uint32_t* r, uint32_t a) {
    asm volatile("ldmatrix.sync.aligned.m8n8.x4.shared.b16 {%0,%1,%2,%3}, [%4];"
        : "=r"(r[0]), "=r"(r[1]), "=r"(r[2]), "=r"(r[3]) : "r"(a));
}
__device__ __forceinline__ void ldsm2(uint32_t* r, uint32_t a) {
    asm volatile("ldmatrix.sync.aligned.m8n8.x2.shared.b16 {%0,%1}, [%2];"
        : "=r"(r[0]), "=r"(r[1]) : "r"(a));
}
__device__ __forceinline__ void cpa16(uint32_t s, const void* g, int ok) {
    asm volatile("cp.async.cg.shared.global [%0], [%1], 16, %2;"
                 :: "r"(s), "l"(g), "r"(ok ? 16 : 0));
}
__device__ __forceinline__ void cpa_commit() { asm volatile("cp.async.commit_group;"); }
template<int N> __device__ __forceinline__ void cpa_wait() {
    asm volatile("cp.async.wait_group %0;" :: "n"(N));
}

// ================= GEMM core: elem-major tiles, ldmatrix fragments =================
// Tile stage: 128 elems x 16 kp words, smem row stride 20 words (conflict-free ldmatrix).
// Per buffer: Ah@0, Al@2560, Bh@5120, Bl@7680 (words); buffer stride 10240 words.
struct GemmPtrs {
    const uint32_t *Ah, *Al, *Bh, *Bl;
    int lda, ldb, KP;   // gmem row strides (words), total k-pairs
    bool sameAB;
};

__device__ __forceinline__ void gemm_mainloop(
    const GemmPtrs& P, uint32_t* smbuf, int tid, int wm, int wn, int lane,
    float acc[4][4][4])
{
    const uint32_t smbase = (uint32_t)__cvta_generic_to_shared(smbuf);
    const int KT = (P.KP + 15) / 16;
    const bool same = P.sameAB;
    const uint32_t aoff = (uint32_t)((lane & 15) * 20 + ((lane >> 4) << 2)) * 4u;
    const uint32_t boff = (uint32_t)((lane & 7) * 20 + (((lane >> 3) & 1) << 2)) * 4u;

    auto issue = [&](int kt, int buf) {
        const int ko = kt * 16;
        const uint32_t bb = smbase + (uint32_t)buf * (10240u * 4u);
        #pragma unroll
        for (int i = 0; i < 2; i++) {
            int idx = tid + i * 256;
            int e = idx >> 2, q = (idx & 3) << 2;
            uint32_t d = bb + (uint32_t)(e * 20 + q) * 4u;
            int ok = (ko + q) < P.KP;
            cpa16(d,             P.Ah + (size_t)e * P.lda + ko + q, ok);
            cpa16(d + 2560u * 4, P.Al + (size_t)e * P.lda + ko + q, ok);
            if (!same) {
                cpa16(d + 5120u * 4, P.Bh + (size_t)e * P.ldb + ko + q, ok);
                cpa16(d + 7680u * 4, P.Bl + (size_t)e * P.ldb + ko + q, ok);
            }
        }
        cpa_commit();
    };

    issue(0, 0);
    for (int kt = 0; kt < KT; kt++) {
        const int cur = kt & 1;
        if (kt + 1 < KT) { issue(kt + 1, cur ^ 1); cpa_wait<1>(); }
        else             { cpa_wait<0>(); }
        __syncthreads();
        const uint32_t bb = smbase + (uint32_t)cur * (10240u * 4u);
        const uint32_t bAh = bb, bAl = bb + 2560u * 4;
        const uint32_t bBh = same ? bb : bb + 5120u * 4;
        const uint32_t bBl = same ? bb + 2560u * 4 : bb + 7680u * 4;
        #pragma unroll
        for (int kk = 0; kk < 2; kk++) {
            const uint32_t kbo = (uint32_t)(kk * 8) * 4u;
            uint32_t ah[4][4], al[4][4], bh[4][2], bl[4][2];
            #pragma unroll
            for (int mt = 0; mt < 4; mt++) {
                uint32_t ro = (uint32_t)((wm * 64 + mt * 16) * 20) * 4u;
                ldsm4(ah[mt], bAh + aoff + ro + kbo);
                ldsm4(al[mt], bAl + aoff + ro + kbo);
            }
            #pragma unroll
            for (int nt = 0; nt < 4; nt++) {
                uint32_t co = (uint32_t)((wn * 32 + nt * 8) * 20) * 4u;
                ldsm2(bh[nt], bBh + boff + co + kbo);
                ldsm2(bl[nt], bBl + boff + co + kbo);
            }
            #pragma unroll
            for (int mt = 0; mt < 4; mt++)
                #pragma unroll
                for (int nt = 0; nt < 4; nt++) {
                    mma16(acc[mt][nt], ah[mt], bh[nt]);
                    mma16(acc[mt][nt], al[mt], bh[nt]);
                    mma16(acc[mt][nt], ah[mt], bl[nt]);
                }
        }
        __syncthreads();
    }
}

// ================= plain / pooled GEMM =================
template<bool POOL>
__global__ void __launch_bounds__(256) gemm16(
    const uint32_t* __restrict__ Ahg, const uint32_t* __restrict__ Alg,
    const uint32_t* __restrict__ Bhg, const uint32_t* __restrict__ Blg,
    float* __restrict__ Cc, const float* __restrict__ bne,
    int KP, int lda, int ldb, int ldc, size_t sAz, size_t sBz, size_t sCz)
{
    extern __shared__ __align__(16) uint32_t smbuf[];
    const int z = blockIdx.z;
    const int m0 = blockIdx.y * 128, n0 = blockIdx.x * 128;
    const int tid = threadIdx.x, lane = tid & 31, wrp = tid >> 5;
    const int wm = wrp >> 2, wn = wrp & 3;
    const int qr = lane >> 2, qc = lane & 3;

    float acc[4][4][4];
    #pragma unroll
    for (int i = 0; i < 4; i++)
        #pragma unroll
        for (int j = 0; j < 4; j++)
            #pragma unroll
            for (int q = 0; q < 4; q++) acc[i][j][q] = 0.f;

    GemmPtrs P{Ahg + z * sAz + (size_t)m0 * lda, Alg + z * sAz + (size_t)m0 * lda,
               Bhg + z * sBz + (size_t)n0 * ldb, Blg + z * sBz + (size_t)n0 * ldb,
               lda, ldb, KP, false};
    gemm_mainloop(P, smbuf, tid, wm, wn, lane, acc);

    if (!POOL) {
        float* Cb = Cc + z * sCz;
        #pragma unroll
        for (int mt = 0; mt < 4; mt++)
            #pragma unroll
            for (int nt = 0; nt < 4; nt++) {
                int r = m0 + wm * 64 + mt * 16 + qr;
                int cc = n0 + wn * 32 + nt * 8 + 2 * qc;
                *(float2*)(Cb + (size_t)r * ldc + cc)       = make_float2(acc[mt][nt][0], acc[mt][nt][1]);
                *(float2*)(Cb + (size_t)(r + 8) * ldc + cc) = make_float2(acc[mt][nt][2], acc[mt][nt][3]);
            }
    } else {
        __shared__ float smax[128][5], ssum[128][5];
        #pragma unroll
        for (int mt = 0; mt < 4; mt++) {
            int rl2 = wm * 64 + mt * 16 + qr;
            int o0 = m0 + rl2, o1 = o0 + 8;
            float s0 = bne[o0] / sqrtf(bne[3072 + o0] + CEPS);
            float b0 = bne[1024 + o0], u0 = bne[2048 + o0];
            float s1 = bne[o1] / sqrtf(bne[3072 + o1] + CEPS);
            float b1 = bne[1024 + o1], u1 = bne[2048 + o1];
            float mx0 = -INFINITY, sm0 = 0.f, mx1 = -INFINITY, sm1 = 0.f;
            #pragma unroll
            for (int nt = 0; nt < 4; nt++) {
                #pragma unroll
                for (int p = 0; p < 2; p++) {
                    float y0 = (acc[mt][nt][p] - u0) * s0 + b0;
                    y0 = (y0 > 0.f) ? y0 : CSLOPE * y0;
                    mx0 = fmaxf(mx0, y0); sm0 += y0;
                    float y1 = (acc[mt][nt][2 + p] - u1) * s1 + b1;
                    y1 = (y1 > 0.f) ? y1 : CSLOPE * y1;
                    mx1 = fmaxf(mx1, y1); sm1 += y1;
                }
            }
            #pragma unroll
            for (int off = 1; off <= 2; off <<= 1) {
                mx0 = fmaxf(mx0, __shfl_xor_sync(0xffffffffu, mx0, off));
                sm0 += __shfl_xor_sync(0xffffffffu, sm0, off);
                mx1 = fmaxf(mx1, __shfl_xor_sync(0xffffffffu, mx1, off));
                sm1 += __shfl_xor_sync(0xffffffffu, sm1, off);
            }
            if (qc == 0) {
                smax[rl2][wn] = mx0; ssum[rl2][wn] = sm0;
                smax[rl2 + 8][wn] = mx1; ssum[rl2 + 8][wn] = sm1;
            }
        }
        __syncthreads();
        if (tid < 128) {
            float mx = -INFINITY, sm = 0.f;
            #pragma unroll
            for (int w = 0; w < 4; w++) { mx = fmaxf(mx, smax[tid][w]); sm += ssum[tid][w]; }
            size_t o = (size_t)z * NPTS + m0 + tid;
            g_pmax[o * 8 + blockIdx.x] = mx;
            g_psum[o * 8 + blockIdx.x] = sm;
        }
    }
}

// ================= merged symmetric-gram + Z =================
// blocks [0,36): lower-triangle gram tiles (mirror transpose write);
// blocks [36, 36+8*ZT): Z = cat @ Wt.
__global__ void __launch_bounds__(256) gramz_kernel(
    const uint32_t* __restrict__ catH, const uint32_t* __restrict__ catL, int cpw,
    const uint32_t* __restrict__ WtHs, const uint32_t* __restrict__ WtLs,
    float* __restrict__ G, float* __restrict__ Z,
    int KP, int ZT, int ld2O)
{
    extern __shared__ __align__(16) uint32_t smbuf[];
    const int z = blockIdx.z;
    const int t = blockIdx.x;
    const int tid = threadIdx.x, lane = tid & 31, wrp = tid >> 5;
    const int wm = wrp >> 2, wn = wrp & 3;
    const int qr = lane >> 2, qc = lane & 3;

    int m0, n0, ldb_, ldc_;
    const uint32_t *Ahp, *Alp, *Bhp, *Blp;
    float* Cb;
    bool mirror = false, same = false;

    if (t < 36) {
        int ib = 0;
        while ((ib + 1) * (ib + 2) / 2 <= t) ib++;
        int ia = t - ib * (ib + 1) / 2;
        m0 = ia * 128; n0 = ib * 128;
        Ahp = catH + ((size_t)z * NPTS + m0) * 256 + cpw;
        Alp = catL + ((size_t)z * NPTS + m0) * 256 + cpw;
        Bhp = catH + ((size_t)z * NPTS + n0) * 256 + cpw;
        Blp = catL + ((size_t)z * NPTS + n0) * 256 + cpw;
        ldb_ = 256; ldc_ = NPTS;
        Cb = G + (size_t)z * NPTS * NPTS;
        mirror = (ia != ib);
        same = (ia == ib);
    } else {
        int t2 = t - 36;
        m0 = (t2 / ZT) * 128; n0 = (t2 % ZT) * 128;
        Ahp = catH + ((size_t)z * NPTS + m0) * 256 + cpw;
        Alp = catL + ((size_t)z * NPTS + m0) * 256 + cpw;
        Bhp = WtHs + (size_t)n0 * KP;
        Blp = WtLs + (size_t)n0 * KP;
        ldb_ = KP; ldc_ = ld2O;
        Cb = Z + (size_t)z * NPTS * ld2O;
    }

    float acc[4][4][4];
    #pragma unroll
    for (int i = 0; i < 4; i++)
        #pragma unroll
        for (int j = 0; j < 4; j++)
            #pragma unroll
            for (int q = 0; q < 4; q++) acc[i][j][q] = 0.f;

    GemmPtrs P{Ahp, Alp, Bhp, Blp, 256, ldb_, KP, same};
    gemm_mainloop(P, smbuf, tid, wm, wn, lane, acc);

    #pragma unroll
    for (int mt = 0; mt < 4; mt++)
        #pragma unroll
        for (int nt = 0; nt < 4; nt++) {
            int r = m0 + wm * 64 + mt * 16 + qr;
            int cc = n0 + wn * 32 + nt * 8 + 2 * qc;
            *(float2*)(Cb + (size_t)r * ldc_ + cc)       = make_float2(acc[mt][nt][0], acc[mt][nt][1]);
            *(float2*)(Cb + (size_t)(r + 8) * ldc_ + cc) = make_float2(acc[mt][nt][2], acc[mt][nt][3]);
        }

    if (mirror) {
        float* S = (float*)smbuf;   // 128 x 132 floats = 67.6KB (fits 81.9KB)
        __syncthreads();
        #pragma unroll
        for (int mt = 0; mt < 4; mt++)
            #pragma unroll
            for (int nt = 0; nt < 4; nt++) {
                int rl = wm * 64 + mt * 16 + qr;
                int cl = wn * 32 + nt * 8 + 2 * qc;
                S[(size_t)cl * 132 + rl]           = acc[mt][nt][0];
                S[(size_t)(cl + 1) * 132 + rl]     = acc[mt][nt][1];
                S[(size_t)cl * 132 + rl + 8]       = acc[mt][nt][2];
                S[(size_t)(cl + 1) * 132 + rl + 8] = acc[mt][nt][3];
            }
        __syncthreads();
        #pragma unroll
        for (int idx = tid; idx < 4096; idx += 256) {
            int row = idx >> 5, q = idx & 31;
            float4 v = *(const float4*)&S[(size_t)row * 132 + 4 * q];
            *(float4*)(Cb + (size_t)(n0 + row) * NPTS + m0 + 4 * q) = v;
        }
    }
}

// ================= block-1 topk: selection only =================
__global__ void __launch_bounds__(256) topk3_kernel(const float* __restrict__ x) {
    const int tid = threadIdx.x, lane = tid & 31;
    const int gw = blockIdx.x * 8 + (tid >> 5);
    const int b = gw >> 10, n = gw & 1023;
    const float* xb = x + (size_t)b * 3 * NPTS;
    float c0 = xb[n], c1 = xb[NPTS + n], c2 = xb[2 * NPTS + n];
    float d[32];
    #pragma unroll
    for (int j = 0; j < 32; j++) {
        int m = j * 32 + lane;
        float v0 = xb[m], v1 = xb[NPTS + m], v2 = xb[2 * NPTS + m];
        float dot = fmaf(v2, c2, fmaf(v1, c1, fmaf(v0, c0, 0.f)));
        float xxm = fmaf(v2, v2, fmaf(v1, v1, fmaf(v0, v0, 0.f)));
        d[j] = 2.f * dot - xxm;
    }
    int* myidx = g_idx + ((size_t)b * NPTS + n) * KNB;
    float lm = -INFINITY; int lj = 0;
    #pragma unroll
    for (int j = 0; j < 32; j++) if (d[j] > lm) { lm = d[j]; lj = j; }
    for (int k = 0; k < KNB; k++) {
        float bv = lm; int bidx = lj * 32 + lane;
        #pragma unroll
        for (int off = 16; off > 0; off >>= 1) {
            float ov = __shfl_xor_sync(0xffffffffu, bv, off);
            int   oi = __shfl_xor_sync(0xffffffffu, bidx, off);
            if (ov > bv || (ov == bv && oi < bidx)) { bv = ov; bidx = oi; }
        }
        if (lane == (bidx & 31)) {
            int jj = bidx >> 5;
            lm = -INFINITY; lj = 0;
            #pragma unroll
            for (int j = 0; j < 32; j++) {
                if (j == jj) d[j] = -INFINITY;
                if (d[j] > lm) { lm = d[j]; lj = j; }
            }
        }
        if (lane == 0) myidx[k] = bidx;
    }
}

// ================= fused topk + conv-epilogue =================
template<int O, bool WX, bool SEL>
__global__ void __launch_bounds__(256) tkcepi_kernel(const float* __restrict__ bnp, int cout_off) {
    constexpr int NCH = O / 32;
    const int tid = threadIdx.x, lane = tid & 31, wrp = tid >> 5;
    const int b = blockIdx.y;
    const int n = blockIdx.x * 8 + wrp;
    __shared__ float ys[8][O + 2];
    __shared__ int jids[8][KNB];

    int mysel = 0;
    if (SEL) {
        const float* Grow = g_gram + ((size_t)b * NPTS + n) * NPTS;
        const float* xxb = g_xx + b * NPTS;
        float d[32];
        #pragma unroll
        for (int j = 0; j < 32; j++) {
            int m = j * 32 + lane;
            d[j] = 2.f * Grow[m] - xxb[m];
        }
        float lm = -INFINITY; int lj = 0;
        #pragma unroll
        for (int j = 0; j < 32; j++) if (d[j] > lm) { lm = d[j]; lj = j; }
        for (int k = 0; k < KNB; k++) {
            float bv = lm; int bidx = lj * 32 + lane;
            #pragma unroll
            for (int off = 16; off > 0; off >>= 1) {
                float ov = __shfl_xor_sync(0xffffffffu, bv, off);
                int   oi = __shfl_xor_sync(0xffffffffu, bidx, off);
                if (ov > bv || (ov == bv && oi < bidx)) { bv = ov; bidx = oi; }
            }
            if (lane == (bidx & 31)) {
                int jj = bidx >> 5;
                lm = -INFINITY; lj = 0;
                #pragma unroll
                for (int j = 0; j < 32; j++) {
                    if (j == jj) d[j] = -INFINITY;
                    if (d[j] > lm) { lm = d[j]; lj = j; }
                }
            }
            if (lane == k) mysel = bidx;
        }
    } else {
        if (lane < KNB) mysel = g_idx[((size_t)b * NPTS + n) * KNB + lane];
    }
    if (lane < KNB) jids[wrp][lane] = mysel;
    __syncwarp();

    const int ld = 2 * O;
    const size_t rowbase = (size_t)b * NPTS;
    float mx[NCH];
    #pragma unroll
    for (int ch = 0; ch < NCH; ch++) mx[ch] = -INFINITY;
    #pragma unroll 4
    for (int k = 0; k < KNB; k++) {
        const float* Zr = g_Z + (rowbase + jids[wrp][k]) * ld;
        #pragma unroll
        for (int ch = 0; ch < NCH; ch++)
            mx[ch] = fmaxf(mx[ch], Zr[ch * 32 + lane]);
    }
    const float* Zc = g_Z + (rowbase + n) * ld + O;
    float xs = 0.f;
    #pragma unroll
    for (int ch = 0; ch < NCH; ch++) {
        int o = ch * 32 + lane;
        float v = mx[ch] + Zc[o];
        float scale = bnp[o] / sqrtf(bnp[3 * O + o] + CEPS);
        float y = (v - bnp[2 * O + o]) * scale + bnp[O + o];
        y = (y > 0.f) ? y : CSLOPE * y;
        ys[wrp][o] = y;
        if (WX) xs = fmaf(y, y, xs);
    }
    if (WX) {
        #pragma unroll
        for (int off = 16; off > 0; off >>= 1) xs += __shfl_xor_sync(0xffffffffu, xs, off);
        if (lane == 0) g_xx[b * NPTS + n] = xs;
    }
    __syncthreads();

    // elem-major cat write: per point, O/2 contiguous pair-words
    const int cpw0 = cout_off >> 1;
    constexpr int HP = O / 2;
    #pragma unroll
    for (int i = tid; i < 8 * HP; i += 256) {
        int cp = i % HP, nl = i / HP;
        float y0 = ys[nl][2 * cp], y1 = ys[nl][2 * cp + 1];
        size_t w = ((size_t)b * NPTS + blockIdx.x * 8 + nl) * 256 + cpw0 + cp;
        g_catH[w] = packh(y0, y1);
        g_catL[w] = packl(y0, y1);
    }
}

// ================= pack =================
__global__ void __launch_bounds__(256) pack_kernel(
    const float* __restrict__ x,
    const float* __restrict__ w0, const float* __restrict__ w1,
    const float* __restrict__ w2, const float* __restrict__ w3,
    const float* __restrict__ we)
{
    const int gstride = gridDim.x * 256;
    int gid = blockIdx.x * 256 + threadIdx.x;

    // we: [o][p], p fastest (coalesced read + write)
    for (int i = gid; i < 1024 * 256; i += gstride) {
        int o = i >> 8, p = i & 255;
        float v0 = we[(size_t)o * 512 + 2 * p];
        float v1 = we[(size_t)o * 512 + 2 * p + 1];
        g_weTH[i] = packh(v0, v1);
        g_weTL[i] = packl(v0, v1);
    }
    // x: [b*NPTS+n][4], pairs (x0,x1),(x2,0),0,0
    for (int i = gid; i < BATCH * NPTS; i += gstride) {
        const float* xr = x + (size_t)(i >> 10) * 3 * NPTS;
        int nn = i & 1023;
        float v0 = xr[nn], v1 = xr[NPTS + nn], v2 = xr[2 * NPTS + nn];
        g_xH[i * 4 + 0] = packh(v0, v1); g_xL[i * 4 + 0] = packl(v0, v1);
        g_xH[i * 4 + 1] = packh(v2, 0.f); g_xL[i * 4 + 1] = packl(v2, 0.f);
        g_xH[i * 4 + 2] = 0u; g_xL[i * 4 + 2] = 0u;
        g_xH[i * 4 + 3] = 0u; g_xL[i * 4 + 3] = 0u;
    }
    // conv weights: [j][kp] per segment (j<O: W1 row j; j>=O: Wd row j-O)
    for (int i = gid; i < WTOTU; i += gstride) {
        const float* w; int C, O, KPs, loc;
        if (i < WSEG1)      { w = w0; C = 3;   O = 64;  KPs = 4;  loc = i - WSEG0; }
        else if (i < WSEG2) { w = w1; C = 64;  O = 64;  KPs = 32; loc = i - WSEG1; }
        else if (i < WSEG3) { w = w2; C = 64;  O = 128; KPs = 32; loc = i - WSEG2; }
        else                { w = w3; C = 128; O = 256; KPs = 64; loc = i - WSEG3; }
        int j = loc / KPs, kp = loc % KPs;
        int k0 = 2 * kp, k1 = 2 * kp + 1;
        float v0 = 0.f, v1 = 0.f;
        if (j < O) {
            if (k0 < C) v0 = w[(size_t)j * 2 * C + k0];
            if (k1 < C) v1 = w[(size_t)j * 2 * C + k1];
        } else {
            int o = j - O;
            if (k0 < C) v0 = w[(size_t)o * 2 * C + C + k0] - w[(size_t)o * 2 * C + k0];
            if (k1 < C) v1 = w[(size_t)o * 2 * C + C + k1] - w[(size_t)o * 2 * C + k1];
        }
        g_WtH[i] = packh(v0, v1);
        g_WtL[i] = packl(v0, v1);
    }
}

// ================= MLP head, stage 1 =================
__global__ void __launch_bounds__(512) head1_kernel(
    const float* __restrict__ wf0, const float* __restrict__ bnf0)
{
    const int b = blockIdx.x, q = blockIdx.y;
    const int tid = threadIdx.x;
    const int w = tid >> 5, lane = tid & 31;
    __shared__ float h0s[2048];

    for (int o = tid; o < 1024; o += 512) {
        size_t base = ((size_t)b * NPTS + o) * 8;
        float mx = -INFINITY, sm = 0.f;
        #pragma unroll
        for (int t = 0; t < 8; t++) { mx = fmaxf(mx, g_pmax[base + t]); sm += g_psum[base + t]; }
        h0s[o] = mx;
        h0s[1024 + o] = sm * (1.0f / 1024.0f);
    }
    __syncthreads();

    for (int j = 0; j < 8; j++) {
        int o = q * 128 + w * 8 + j;
        const float* wr = wf0 + (size_t)o * 2048;
        float a = 0.f;
        #pragma unroll 4
        for (int c = lane * 4; c < 2048; c += 128) {
            float4 wv = *(const float4*)(wr + c);
            a = fmaf(wv.x, h0s[c], a);
            a = fmaf(wv.y, h0s[c + 1], a);
            a = fmaf(wv.z, h0s[c + 2], a);
            a = fmaf(wv.w, h0s[c + 3], a);
        }
        #pragma unroll
        for (int off = 16; off > 0; off >>= 1) a += __shfl_xor_sync(0xffffffffu, a, off);
        if (lane == 0) {
            float scale = bnf0[o] / sqrtf(bnf0[1536 + o] + CEPS);
            float y = (a - bnf0[1024 + o]) * scale + bnf0[512 + o];
            g_h1[b * 512 + o] = (y > 0.f) ? y : CSLOPE * y;
        }
    }
}

// ================= MLP head, stage 2 =================
__global__ void __launch_bounds__(512) head2_kernel(
    const float* __restrict__ wf1, const float* __restrict__ bnf1,
    const float* __restrict__ wfin, const float* __restrict__ bfin,
    float* __restrict__ out)
{
    const int b = blockIdx.x, tid = threadIdx.x;
    const int w = tid >> 5, lane = tid & 31;
    __shared__ float h1s[512];
    __shared__ float h2s[256];

    h1s[tid] = g_h1[b * 512 + tid];
    __syncthreads();

    for (int j = 0; j < 16; j++) {
        int o = w * 16 + j;
        const float* wr = wf1 + (size_t)o * 512;
        float a = 0.f;
        #pragma unroll
        for (int c = lane * 4; c < 512; c += 128) {
            float4 wv = *(const float4*)(wr + c);
            a = fmaf(wv.x, h1s[c], a);
            a = fmaf(wv.y, h1s[c + 1], a);
            a = fmaf(wv.z, h1s[c + 2], a);
            a = fmaf(wv.w, h1s[c + 3], a);
        }
        #pragma unroll
        for (int off = 16; off > 0; off >>= 1) a += __shfl_xor_sync(0xffffffffu, a, off);
        if (lane == 0) {
            float scale = bnf1[o] / sqrtf(bnf1[768 + o] + CEPS);
            float y = (a - bnf1[512 + o]) * scale + bnf1[256 + o];
            h2s[o] = (y > 0.f) ? y : CSLOPE * y;
        }
    }
    __syncthreads();

    for (int j = 0; j < 4; j++) {
        int o = w * 4 + j;
        const float* wr = wfin + (size_t)o * 256;
        float a = 0.f;
        #pragma unroll
        for (int c = lane * 4; c < 256; c += 128) {
            float4 wv = *(const float4*)(wr + c);
            a = fmaf(wv.x, h2s[c], a);
            a = fmaf(wv.y, h2s[c + 1], a);
            a = fmaf(wv.z, h2s[c + 2], a);
            a = fmaf(wv.w, h2s[c + 3], a);
        }
        #pragma unroll
        for (int off = 16; off > 0; off >>= 1) a += __shfl_xor_sync(0xffffffffu, a, off);
        if (lane == 0) out[b * 64 + o] = bfin[o] + a;
    }
}

// ================= launch =================
#define GSMEM 81920

extern "C" void kernel_launch(void* const* d_in, const int* in_sizes, int n_in,
                              void* d_out, int out_size) {
    const float* x    = (const float*)d_in[0];
    const float* w0   = (const float*)d_in[1];
    const float* w1   = (const float*)d_in[2];
    const float* w2   = (const float*)d_in[3];
    const float* w3   = (const float*)d_in[4];
    const float* bn0  = (const float*)d_in[5];
    const float* bn1  = (const float*)d_in[6];
    const float* bn2  = (const float*)d_in[7];
    const float* bn3  = (const float*)d_in[8];
    const float* we   = (const float*)d_in[9];
    const float* bne  = (const float*)d_in[10];
    const float* wf0  = (const float*)d_in[11];
    const float* bnf0 = (const float*)d_in[12];
    const float* wf1  = (const float*)d_in[13];
    const float* bnf1 = (const float*)d_in[14];
    const float* wfin = (const float*)d_in[15];
    const float* bfin = (const float*)d_in[16];

    static bool s_init = false;
    static cudaStream_t s1;
    static cudaEvent_t evS, evJ0;
    if (!s_init) {
        cudaStreamCreateWithFlags(&s1, cudaStreamNonBlocking);
        cudaEventCreateWithFlags(&evS, cudaEventDisableTiming);
        cudaEventCreateWithFlags(&evJ0, cudaEventDisableTiming);
        cudaFuncSetAttribute(gemm16<false>, cudaFuncAttributeMaxDynamicSharedMemorySize, GSMEM);
        cudaFuncSetAttribute(gemm16<true>,  cudaFuncAttributeMaxDynamicSharedMemorySize, GSMEM);
        cudaFuncSetAttribute(gramz_kernel,  cudaFuncAttributeMaxDynamicSharedMemorySize, GSMEM);
        s_init = true;
    }

    float *Zp, *gramp;
    uint32_t *catHp, *catLp, *WtHp, *WtLp, *weTHp, *weTLp, *xHp, *xLp;
    cudaGetSymbolAddress((void**)&Zp, g_Z);
    cudaGetSymbolAddress((void**)&gramp, g_gram);
    cudaGetSymbolAddress((void**)&catHp, g_catH);
    cudaGetSymbolAddress((void**)&catLp, g_catL);
    cudaGetSymbolAddress((void**)&WtHp, g_WtH);
    cudaGetSymbolAddress((void**)&WtLp, g_WtL);
    cudaGetSymbolAddress((void**)&weTHp, g_weTH);
    cudaGetSymbolAddress((void**)&weTLp, g_weTL);
    cudaGetSymbolAddress((void**)&xHp, g_xH);
    cudaGetSymbolAddress((void**)&xLp, g_xL);

    dim3 gtk(128, BATCH);
    cudaStream_t s0 = 0;

    // fork: pack + Z1 on s1; topk3 on main
    cudaEventRecord(evS, s0);
    cudaStreamWaitEvent(s1, evS, 0);
    pack_kernel<<<256, 256, 0, s1>>>(x, w0, w1, w2, w3, we);
    topk3_kernel<<<1024, 256>>>(x);
    gemm16<false><<<dim3(1, 8, BATCH), 256, GSMEM, s1>>>(
        xHp, xLp, WtHp + WSEG0, WtLp + WSEG0, Zp, nullptr,
        4, 4, 4, 128, (size_t)NPTS * 4, 0, (size_t)NPTS * 128);
    cudaEventRecord(evJ0, s1);
    cudaStreamWaitEvent(s0, evJ0, 0);
    tkcepi_kernel<64, true, false><<<gtk, 256>>>(bn0, 0);

    // block 2: gram + Z2 (cat cp [0,32))
    gramz_kernel<<<dim3(36 + 8, 1, BATCH), 256, GSMEM>>>(
        catHp, catLp, 0, WtHp + WSEG1, WtLp + WSEG1, gramp, Zp, 32, 1, 128);
    tkcepi_kernel<64, true, true><<<gtk, 256>>>(bn1, 64);

    // block 3: gram + Z3 (cat cp [32,64))
    gramz_kernel<<<dim3(36 + 16, 1, BATCH), 256, GSMEM>>>(
        catHp, catLp, 32, WtHp + WSEG2, WtLp + WSEG2, gramp, Zp, 32, 2, 256);
    tkcepi_kernel<128, true, true><<<gtk, 256>>>(bn2, 128);

    // block 4: gram + Z4 (cat cp [64,128))
    gramz_kernel<<<dim3(36 + 32, 1, BATCH), 256, GSMEM>>>(
        catHp, catLp, 64, WtHp + WSEG3, WtLp + WSEG3, gramp, Zp, 64, 4, 512);
    tkcepi_kernel<256, false, true><<<gtk, 256>>>(bn3, 256);

    // embedding GEMM, full K (256 pairs), fused BN+lrelu+pool partials
    gemm16<true><<<dim3(8, 8, BATCH), 256, GSMEM>>>(
        weTHp, weTLp, catHp, catLp, nullptr, bne,
        256, 256, 256, 0, 0, (size_t)NPTS * 256, 0);

    // split MLP head
    head1_kernel<<<dim3(BATCH, 4), 512>>>(wf0, bnf0);
    head2_kernel<<<BATCH, 512>>>(wf1, bnf1, wfin, bfin, (float*)d_out);
}